// round 7
// baseline (speedup 1.0000x reference)
#include <cuda_runtime.h>
#include <cuda_bf16.h>

#define NMAX 50000
#define EMAX 800000
#define DIM  128
#define NG   64

// ---------------- device scratch (static, no runtime allocation) ------------
__device__ float g_deg[NMAX];
__device__ float g_dinv[NMAX];
__device__ int   g_cnt[NMAX];
__device__ int   g_off[NMAX + 1];
__device__ int   g_cursor[NMAX];
__device__ int   g_esrc[EMAX + NMAX];
__device__ float g_enorm[EMAX + NMAX];
__device__ float g_B0[(size_t)NMAX * DIM];
__device__ float g_B1[(size_t)NMAX * DIM];
__device__ float g_pooled[NG * DIM];
__device__ int   g_gcnt[NG];

// ---------------- small init kernels ---------------------------------------
__global__ void zero_small_k() {
    int t = threadIdx.x;
    for (int i = t; i < NG * DIM; i += blockDim.x) g_pooled[i] = 0.f;
    if (t < NG) g_gcnt[t] = 0;
}

__global__ void node_init_k(const int* __restrict__ batch, int n) {
    int i = blockIdx.x * blockDim.x + threadIdx.x;
    if (i < n) {
        g_deg[i] = 1.0f;   // self-loop weight
        g_cnt[i] = 1;      // self-loop CSR slot
        atomicAdd(&g_gcnt[batch[i]], 1);
    }
}

__global__ void edge_count_k(const int* __restrict__ col,
                             const float* __restrict__ ew, int ne) {
    int e = blockIdx.x * blockDim.x + threadIdx.x;
    if (e < ne) {
        int c = col[e];
        atomicAdd(&g_deg[c], ew[e]);
        atomicAdd(&g_cnt[c], 1);
    }
}

__global__ void dinv_k(int n) {
    int i = blockIdx.x * blockDim.x + threadIdx.x;
    if (i < n) g_dinv[i] = rsqrtf(g_deg[i]);   // deg >= 1 always (self loop)
}

// single-block exclusive scan of g_cnt -> g_off (n up to 50176)
__global__ __launch_bounds__(1024) void scan_k(int n) {
    int tid = threadIdx.x;
    int chunk = (n + 1023) >> 10;
    int begin = min(tid * chunk, n);
    int end = min(begin + chunk, n);
    int s = 0;
    for (int i = begin; i < end; i++) s += g_cnt[i];

    int lane = tid & 31, wid = tid >> 5;
    int v = s;
#pragma unroll
    for (int o = 1; o < 32; o <<= 1) {
        int t = __shfl_up_sync(0xFFFFFFFFu, v, o);
        if (lane >= o) v += t;
    }
    __shared__ int ws[32];
    if (lane == 31) ws[wid] = v;
    __syncthreads();
    if (wid == 0) {
        int t2 = ws[lane];
#pragma unroll
        for (int o = 1; o < 32; o <<= 1) {
            int t = __shfl_up_sync(0xFFFFFFFFu, t2, o);
            if (lane >= o) t2 += t;
        }
        ws[lane] = t2;
    }
    __syncthreads();
    int exc = v - s + (wid ? ws[wid - 1] : 0);
    int run = exc;
    for (int i = begin; i < end; i++) { g_off[i] = run; run += g_cnt[i]; }
    if (tid == 1023) g_off[n] = run;   // last thread's run == grand total
}

__global__ void fill_self_k(int n) {
    int i = blockIdx.x * blockDim.x + threadIdx.x;
    if (i < n) {
        int s = g_off[i];
        float di = g_dinv[i];
        g_esrc[s] = i;
        g_enorm[s] = di * di;
        g_cursor[i] = s + 1;
    }
}

__global__ void fill_edges_k(const int* __restrict__ row,
                             const int* __restrict__ col,
                             const float* __restrict__ ew, int ne) {
    int e = blockIdx.x * blockDim.x + threadIdx.x;
    if (e < ne) {
        int r = row[e];
        int c = col[e];
        int pos = atomicAdd(&g_cursor[c], 1);
        g_esrc[pos] = r;
        g_enorm[pos] = g_dinv[r] * ew[e] * g_dinv[c];
    }
}

// ---------------- dense GEMM: C[n,128] = A[n,128] @ B[128,128] --------------
// classic 128x128 tile, BK=8, 8x8 register tile, 256 threads.
// reluIn applies max(0, .) to A elements on load (fuses layer-1 relu).
__global__ __launch_bounds__(256) void gemm_k(const float* __restrict__ A,
                                              const float* __restrict__ B,
                                              float* __restrict__ C,
                                              int n, int reluIn) {
    __shared__ float As[8][128];
    __shared__ float Bs[8][128];
    int tid = threadIdx.x;
    int row0 = blockIdx.x * 128;
    int trow = (tid >> 4) * 8;
    int tcol = (tid & 15) * 8;

    float acc[8][8];
#pragma unroll
    for (int i = 0; i < 8; i++)
#pragma unroll
        for (int j = 0; j < 8; j++) acc[i][j] = 0.f;

    int arow = tid >> 1;          // 0..127
    int ak = (tid & 1) * 4;       // 0 or 4
    int brow = tid >> 5;          // 0..7
    int bcol = (tid & 31) * 4;    // 0..124

#pragma unroll 1
    for (int kt = 0; kt < 16; kt++) {
        int k0 = kt * 8;
        float4 av = make_float4(0.f, 0.f, 0.f, 0.f);
        int gr = row0 + arow;
        if (gr < n) av = *(const float4*)(A + (size_t)gr * DIM + k0 + ak);
        if (reluIn) {
            av.x = fmaxf(av.x, 0.f); av.y = fmaxf(av.y, 0.f);
            av.z = fmaxf(av.z, 0.f); av.w = fmaxf(av.w, 0.f);
        }
        As[ak + 0][arow] = av.x;
        As[ak + 1][arow] = av.y;
        As[ak + 2][arow] = av.z;
        As[ak + 3][arow] = av.w;
        *(float4*)(&Bs[brow][bcol]) = *(const float4*)(B + (size_t)(k0 + brow) * DIM + bcol);
        __syncthreads();

#pragma unroll
        for (int k = 0; k < 8; k++) {
            float ra[8], rb[8];
#pragma unroll
            for (int i = 0; i < 8; i++) ra[i] = As[k][trow + i];
#pragma unroll
            for (int j = 0; j < 8; j++) rb[j] = Bs[k][tcol + j];
#pragma unroll
            for (int i = 0; i < 8; i++)
#pragma unroll
                for (int j = 0; j < 8; j++) acc[i][j] = fmaf(ra[i], rb[j], acc[i][j]);
        }
        __syncthreads();
    }

#pragma unroll
    for (int i = 0; i < 8; i++) {
        int gr = row0 + trow + i;
        if (gr < n) {
            float4 v0 = make_float4(acc[i][0], acc[i][1], acc[i][2], acc[i][3]);
            float4 v1 = make_float4(acc[i][4], acc[i][5], acc[i][6], acc[i][7]);
            *(float4*)(C + (size_t)gr * DIM + tcol) = v0;
            *(float4*)(C + (size_t)gr * DIM + tcol + 4) = v1;
        }
    }
}

// ---------------- SpMM: out[c] = sum_e enorm[e]*X[esrc[e]] + bias -----------
// warp per target node, float4 per lane, 4-edge unroll for MLP.
__global__ void spmm_k(const float* __restrict__ X,
                       const float* __restrict__ bias,
                       float* __restrict__ out, int n) {
    int w = (blockIdx.x * blockDim.x + threadIdx.x) >> 5;
    int lane = threadIdx.x & 31;
    if (w >= n) return;
    int beg = g_off[w], end = g_off[w + 1];
    const float4* X4 = (const float4*)X;
    float4 acc = make_float4(0.f, 0.f, 0.f, 0.f);
    for (int e = beg; e < end; e += 4) {
#pragma unroll
        for (int j = 0; j < 4; j++) {
            int idx = e + j;
            if (idx < end) {
                int r = g_esrc[idx];
                float nv = g_enorm[idx];
                float4 v = __ldg(&X4[(size_t)r * 32 + lane]);
                acc.x = fmaf(nv, v.x, acc.x);
                acc.y = fmaf(nv, v.y, acc.y);
                acc.z = fmaf(nv, v.z, acc.z);
                acc.w = fmaf(nv, v.w, acc.w);
            }
        }
    }
    float4 b4 = ((const float4*)bias)[lane];
    acc.x += b4.x; acc.y += b4.y; acc.z += b4.z; acc.w += b4.w;
    ((float4*)out)[(size_t)w * 32 + lane] = acc;
}

// ---------------- pooling: relu + segment-sum (batch is sorted) -------------
__global__ void pool_k(const float* __restrict__ H,
                       const int* __restrict__ batch, int n) {
    int f = threadIdx.x;                 // 128 threads = features
    int n0 = blockIdx.x * 256;
    int n1 = min(n0 + 256, n);
    if (n0 >= n1) return;
    int g = batch[n0];
    float acc = 0.f;
    for (int i = n0; i < n1; i++) {
        int gi = batch[i];
        if (gi != g) {
            atomicAdd(&g_pooled[g * DIM + f], acc);
            acc = 0.f;
            g = gi;
        }
        acc += fmaxf(H[(size_t)i * DIM + f], 0.f);
    }
    atomicAdd(&g_pooled[g * DIM + f], acc);
}

// ---------------- head: out[g] = dot(pooled[g]/cnt[g], Wh) + bh -------------
__global__ void head_k(const float* __restrict__ Wh,
                       const float* __restrict__ bh,
                       float* __restrict__ out) {
    int g = blockIdx.x;
    int t = threadIdx.x;                 // 128 threads
    float c = fmaxf((float)g_gcnt[g], 1.f);
    float v = g_pooled[g * DIM + t] * Wh[t];
#pragma unroll
    for (int o = 16; o > 0; o >>= 1) v += __shfl_xor_sync(0xFFFFFFFFu, v, o);
    __shared__ float ws[4];
    if ((t & 31) == 0) ws[t >> 5] = v;
    __syncthreads();
    if (t == 0) out[g] = (ws[0] + ws[1] + ws[2] + ws[3]) / c + bh[0];
}

// ---------------- launch -----------------------------------------------------
extern "C" void kernel_launch(void* const* d_in, const int* in_sizes, int n_in,
                              void* d_out, int out_size) {
    const float* x     = (const float*)d_in[0];
    const float* ew    = (const float*)d_in[1];
    const float* W1    = (const float*)d_in[2];
    const float* b1    = (const float*)d_in[3];
    const float* W2    = (const float*)d_in[4];
    const float* b2    = (const float*)d_in[5];
    const float* Wh    = (const float*)d_in[6];
    const float* bh    = (const float*)d_in[7];
    const int*   eidx  = (const int*)d_in[8];   // int32: JAX x64 is disabled
    const int*   batch = (const int*)d_in[9];   // int32

    int E = in_sizes[8] / 2;   // edge_index is (2, E)
    int N = in_sizes[9];
    const int* row = eidx;
    const int* col = eidx + E;

    float *B0p = nullptr, *B1p = nullptr;
    cudaGetSymbolAddress((void**)&B0p, g_B0);
    cudaGetSymbolAddress((void**)&B1p, g_B1);

    int nbN = (N + 255) / 256;
    int nbE = (E + 255) / 256;
    int nbG = (N + 127) / 128;            // gemm blocks
    int nbS = (N * 32 + 255) / 256;       // spmm blocks (warp/node)
    int nbP = (N + 255) / 256;            // pool blocks (256 nodes/block)

    zero_small_k<<<1, 256>>>();
    node_init_k<<<nbN, 256>>>(batch, N);
    edge_count_k<<<nbE, 256>>>(col, ew, E);
    dinv_k<<<nbN, 256>>>(N);
    scan_k<<<1, 1024>>>(N);
    fill_self_k<<<nbN, 256>>>(N);
    fill_edges_k<<<nbE, 256>>>(row, col, ew, E);

    // layer 1: B0 = x @ W1 ; B1 = A_norm @ B0 + b1   (relu deferred)
    gemm_k<<<nbG, 256>>>(x, W1, B0p, N, 0);
    spmm_k<<<nbS, 256>>>(B0p, b1, B1p, N);

    // layer 2: B0 = relu(B1) @ W2 ; B1 = A_norm @ B0 + b2  (relu deferred)
    gemm_k<<<nbG, 256>>>(B1p, W2, B0p, N, 1);
    spmm_k<<<nbS, 256>>>(B0p, b2, B1p, N);

    // pooling (applies relu) + head
    pool_k<<<nbP, 128>>>(B1p, batch, N);
    head_k<<<out_size, 128>>>(Wh, bh, (float*)d_out);
}